// round 10
// baseline (speedup 1.0000x reference)
#include <cuda_runtime.h>
#include <math.h>
#include <stdint.h>

#define D_MODEL 1024
#define NUM_HEADS 16
#define DK 64
#define BATCH 2
#define SEQ 2048
#define M_TOTAL (BATCH * SEQ)  // 4096

// GEMM smem geometry (4-stage cp.async)
#define A_ROW_STRIDE 20
#define A_STAGE_WORDS (128 * A_ROW_STRIDE)
#define B0_STAGE_WORDS (16 * 136)
#define B1_STAGE_WORDS (128 * A_ROW_STRIDE)
#define NSTAGE 4

// flash smem strides:
//  K: LDS.64 at gid*KRS + 2*tig -> need KRS%32==8 -> 72 (cols pair-permuted)
//  V: LDS.32 at tig*VRS + gid   -> need VRS%32==8 -> 72
#define KRS 72
#define VRS 72
#define KB_WORDS (64 * KRS)     // 4608 per buffer
#define VB_WORDS (64 * VRS)     // 4608 per buffer

__device__ float g_q[BATCH * NUM_HEADS * SEQ * DK];
__device__ float g_k[BATCH * NUM_HEADS * SEQ * DK];
__device__ float g_v[BATCH * NUM_HEADS * SEQ * DK];
__device__ float g_cat[M_TOTAL * D_MODEL];

__device__ __forceinline__ uint32_t f2tf(float f) {
    uint32_t u;
    asm("cvt.rna.tf32.f32 %0, %1;" : "=r"(u) : "f"(f));
    return u;
}

__device__ __forceinline__ void mma_tf32(float* c, const uint32_t* a, const uint32_t* b) {
    asm volatile(
        "mma.sync.aligned.m16n8k8.row.col.f32.tf32.tf32.f32 "
        "{%0,%1,%2,%3}, {%4,%5,%6,%7}, {%8,%9}, {%0,%1,%2,%3};"
        : "+f"(c[0]), "+f"(c[1]), "+f"(c[2]), "+f"(c[3])
        : "r"(a[0]), "r"(a[1]), "r"(a[2]), "r"(a[3]), "r"(b[0]), "r"(b[1]));
}
__device__ __forceinline__ void mma_tf32_v(float* c, const uint32_t* a, uint32_t b0, uint32_t b1) {
    asm volatile(
        "mma.sync.aligned.m16n8k8.row.col.f32.tf32.tf32.f32 "
        "{%0,%1,%2,%3}, {%4,%5,%6,%7}, {%8,%9}, {%0,%1,%2,%3};"
        : "+f"(c[0]), "+f"(c[1]), "+f"(c[2]), "+f"(c[3])
        : "r"(a[0]), "r"(a[1]), "r"(a[2]), "r"(a[3]), "r"(b0), "r"(b1));
}

__device__ __forceinline__ void cpa16(uint32_t* smem_dst, const float* gsrc) {
    uint32_t s = (uint32_t)__cvta_generic_to_shared(smem_dst);
    asm volatile("cp.async.cg.shared.global [%0], [%1], 16;" :: "r"(s), "l"(gsrc));
}
__device__ __forceinline__ void cpa4(uint32_t* smem_dst, const float* gsrc) {
    uint32_t s = (uint32_t)__cvta_generic_to_shared(smem_dst);
    asm volatile("cp.async.ca.shared.global [%0], [%1], 4;" :: "r"(s), "l"(gsrc));
}
__device__ __forceinline__ void cpa_commit() {
    asm volatile("cp.async.commit_group;");
}
template <int N>
__device__ __forceinline__ void cpa_wait() {
    asm volatile("cp.async.wait_group %0;" :: "n"(N));
}

// =====================================================================
// TF32 GEMM (R7-R9, known-good): cp.async 4-stage, ONE sync per k-chunk.
// =====================================================================
template <int MODE>
__global__ __launch_bounds__(256, 2) void gemm_v3_kernel(
    const float* __restrict__ X, const float* __restrict__ W,
    const float* __restrict__ bias, float* __restrict__ out)
{
    extern __shared__ uint32_t sg[];
    uint32_t* smA = sg;
    uint32_t* smB = sg + NSTAGE * A_STAGE_WORDS;
    const int BSTW = (MODE == 0) ? B0_STAGE_WORDS : B1_STAGE_WORDS;

    const int t    = threadIdx.x;
    const int n0   = blockIdx.x * 128;
    const int m0   = blockIdx.y * 128;
    const int warp = t >> 5;
    const int lane = t & 31;
    const int gid  = lane >> 2;
    const int tig  = lane & 3;
    const int wm   = (warp & 1) * 64;
    const int wn   = (warp >> 1) * 32;

    const int am[2] = { (t + 0) >> 2, (t + 256) >> 2 };
    const int ak4   = (t & 3) << 2;

    float acc[4][4][4];
#pragma unroll
    for (int i = 0; i < 4; i++)
#pragma unroll
        for (int j = 0; j < 4; j++)
#pragma unroll
            for (int k = 0; k < 4; k++) acc[i][j][k] = 0.f;

    auto issue = [&](int stage, int kc) {
        uint32_t* As_ = smA + stage * A_STAGE_WORDS;
        uint32_t* Bs_ = smB + stage * BSTW;
#pragma unroll
        for (int rep = 0; rep < 2; rep++) {
            int m = am[rep];
            cpa16(As_ + m * A_ROW_STRIDE + ak4,
                  X + (size_t)(m0 + m) * D_MODEL + kc * 16 + ak4);
        }
#pragma unroll
        for (int rep = 0; rep < 2; rep++) {
            int f = t + rep * 256;
            if (MODE == 0) {
                int k = f >> 5, n4 = (f & 31) << 2;
                int bn = n0 + n4;
                int ck = ((k >> 2) & 3) << 2;
                cpa16(Bs_ + k * 136 + (n4 ^ ck),
                      W + (size_t)(bn >> 6) * (D_MODEL * DK)
                        + (size_t)(kc * 16 + k) * DK + (bn & 63));
            } else {
                int n = f >> 2, k4 = (f & 3) << 2;
                cpa16(Bs_ + n * A_ROW_STRIDE + k4,
                      W + (size_t)(n0 + n) * D_MODEL + kc * 16 + k4);
            }
        }
    };

    auto compute = [&](int stage) {
        uint32_t* As_ = smA + stage * A_STAGE_WORDS;
        uint32_t* Bs_ = smB + stage * BSTW;
#pragma unroll
        for (int ks = 0; ks < 2; ks++) {
            const int kb = ks * 8;
            uint32_t af[4][4];
#pragma unroll
            for (int mt = 0; mt < 4; mt++) {
                const int r = (wm + mt * 16 + gid) * A_ROW_STRIDE;
                af[mt][0] = As_[r + kb + tig];
                af[mt][1] = As_[r + 8 * A_ROW_STRIDE + kb + tig];
                af[mt][2] = As_[r + kb + tig + 4];
                af[mt][3] = As_[r + 8 * A_ROW_STRIDE + kb + tig + 4];
            }
            uint32_t bf[4][2];
#pragma unroll
            for (int nt = 0; nt < 4; nt++) {
                const int ncol = wn + nt * 8 + gid;
                if (MODE == 0) {
                    const int x0 = ks ? 8 : 0;
                    const int x1 = ks ? 12 : 4;
                    bf[nt][0] = Bs_[(kb + tig) * 136 + (ncol ^ x0)];
                    bf[nt][1] = Bs_[(kb + tig + 4) * 136 + (ncol ^ x1)];
                } else {
                    bf[nt][0] = Bs_[ncol * A_ROW_STRIDE + kb + tig];
                    bf[nt][1] = Bs_[ncol * A_ROW_STRIDE + kb + tig + 4];
                }
            }
#pragma unroll
            for (int mt = 0; mt < 4; mt++)
#pragma unroll
                for (int nt = 0; nt < 4; nt++) mma_tf32(acc[mt][nt], af[mt], bf[nt]);
        }
    };

    issue(0, 0); cpa_commit();
    issue(1, 1); cpa_commit();
    issue(2, 2); cpa_commit();
    for (int kc = 0; kc < 64; kc++) {
        cpa_wait<2>();
        __syncthreads();
        compute(kc & 3);
        if (kc + 3 < 64) issue((kc + 3) & 3, kc + 3);
        cpa_commit();
    }

#pragma unroll
    for (int mt = 0; mt < 4; mt++) {
#pragma unroll
        for (int nt = 0; nt < 4; nt++) {
            const int r0 = m0 + wm + mt * 16 + gid;
            const int r1 = r0 + 8;
            const int c  = n0 + wn + nt * 8 + tig * 2;
            const float bv0 = bias[c], bv1 = bias[c + 1];
            float2 v0 = make_float2(acc[mt][nt][0] + bv0, acc[mt][nt][1] + bv1);
            float2 v1 = make_float2(acc[mt][nt][2] + bv0, acc[mt][nt][3] + bv1);
            if (MODE == 0) {
                const int h = c >> 6, kd = c & 63;
                const int b0_ = r0 >> 11, s0 = r0 & 2047;
                const int b1_ = r1 >> 11, s1 = r1 & 2047;
                *(float2*)(out + (((size_t)b0_ * NUM_HEADS + h) * SEQ + s0) * DK + kd) = v0;
                *(float2*)(out + (((size_t)b1_ * NUM_HEADS + h) * SEQ + s1) * DK + kd) = v1;
            } else {
                *(float2*)(out + (size_t)r0 * D_MODEL + c) = v0;
                *(float2*)(out + (size_t)r1 * D_MODEL + c) = v1;
            }
        }
    }
}

// proj wrapper (R7-R9, known-good): grid.z selects Q/K/V
struct ProjArgs {
    const float* X[3];
    const float* W[3];
    const float* bias[3];
    float* out[3];
};

__global__ __launch_bounds__(256, 2) void proj_gemm3_v3_kernel(ProjArgs args)
{
    extern __shared__ uint32_t sg[];
    const int z = blockIdx.z;
    const float* X    = args.X[z];
    const float* W    = args.W[z];
    const float* bias = args.bias[z];
    float* out        = args.out[z];

    uint32_t* smA = sg;
    uint32_t* smB = sg + NSTAGE * A_STAGE_WORDS;

    const int t    = threadIdx.x;
    const int n0   = blockIdx.x * 128;
    const int m0   = blockIdx.y * 128;
    const int warp = t >> 5;
    const int lane = t & 31;
    const int gid  = lane >> 2;
    const int tig  = lane & 3;
    const int wm   = (warp & 1) * 64;
    const int wn   = (warp >> 1) * 32;

    const int am[2] = { (t + 0) >> 2, (t + 256) >> 2 };
    const int ak4   = (t & 3) << 2;

    float acc[4][4][4];
#pragma unroll
    for (int i = 0; i < 4; i++)
#pragma unroll
        for (int j = 0; j < 4; j++)
#pragma unroll
            for (int k = 0; k < 4; k++) acc[i][j][k] = 0.f;

    auto issue = [&](int stage, int kc) {
        uint32_t* As_ = smA + stage * A_STAGE_WORDS;
        uint32_t* Bs_ = smB + stage * B0_STAGE_WORDS;
#pragma unroll
        for (int rep = 0; rep < 2; rep++) {
            int m = am[rep];
            cpa16(As_ + m * A_ROW_STRIDE + ak4,
                  X + (size_t)(m0 + m) * D_MODEL + kc * 16 + ak4);
        }
#pragma unroll
        for (int rep = 0; rep < 2; rep++) {
            int f = t + rep * 256;
            int k = f >> 5, n4 = (f & 31) << 2;
            int bn = n0 + n4;
            int ck = ((k >> 2) & 3) << 2;
            cpa16(Bs_ + k * 136 + (n4 ^ ck),
                  W + (size_t)(bn >> 6) * (D_MODEL * DK)
                    + (size_t)(kc * 16 + k) * DK + (bn & 63));
        }
    };

    auto compute = [&](int stage) {
        uint32_t* As_ = smA + stage * A_STAGE_WORDS;
        uint32_t* Bs_ = smB + stage * B0_STAGE_WORDS;
#pragma unroll
        for (int ks = 0; ks < 2; ks++) {
            const int kb = ks * 8;
            const int x0 = ks ? 8 : 0;
            const int x1 = ks ? 12 : 4;
            uint32_t af[4][4];
#pragma unroll
            for (int mt = 0; mt < 4; mt++) {
                const int r = (wm + mt * 16 + gid) * A_ROW_STRIDE;
                af[mt][0] = As_[r + kb + tig];
                af[mt][1] = As_[r + 8 * A_ROW_STRIDE + kb + tig];
                af[mt][2] = As_[r + kb + tig + 4];
                af[mt][3] = As_[r + 8 * A_ROW_STRIDE + kb + tig + 4];
            }
            uint32_t bf[4][2];
#pragma unroll
            for (int nt = 0; nt < 4; nt++) {
                const int ncol = wn + nt * 8 + gid;
                bf[nt][0] = Bs_[(kb + tig) * 136 + (ncol ^ x0)];
                bf[nt][1] = Bs_[(kb + tig + 4) * 136 + (ncol ^ x1)];
            }
#pragma unroll
            for (int mt = 0; mt < 4; mt++)
#pragma unroll
                for (int nt = 0; nt < 4; nt++) mma_tf32(acc[mt][nt], af[mt], bf[nt]);
        }
    };

    issue(0, 0); cpa_commit();
    issue(1, 1); cpa_commit();
    issue(2, 2); cpa_commit();
    for (int kc = 0; kc < 64; kc++) {
        cpa_wait<2>();
        __syncthreads();
        compute(kc & 3);
        if (kc + 3 < 64) issue((kc + 3) & 3, kc + 3);
        cpa_commit();
    }

#pragma unroll
    for (int mt = 0; mt < 4; mt++) {
#pragma unroll
        for (int nt = 0; nt < 4; nt++) {
            const int r0 = m0 + wm + mt * 16 + gid;
            const int r1 = r0 + 8;
            const int c  = n0 + wn + nt * 8 + tig * 2;
            const float bv0 = bias[c], bv1 = bias[c + 1];
            float2 v0 = make_float2(acc[mt][nt][0] + bv0, acc[mt][nt][1] + bv1);
            float2 v1 = make_float2(acc[mt][nt][2] + bv0, acc[mt][nt][3] + bv1);
            const int h = c >> 6, kd = c & 63;
            const int b0_ = r0 >> 11, s0 = r0 & 2047;
            const int b1_ = r1 >> 11, s1 = r1 & 2047;
            *(float2*)(out + (((size_t)b0_ * NUM_HEADS + h) * SEQ + s0) * DK + kd) = v0;
            *(float2*)(out + (((size_t)b1_ * NUM_HEADS + h) * SEQ + s1) * DK + kd) = v1;
        }
    }
}

// =====================================================================
// Flash attention v8: register-resident P (K rows permuted) + K columns
// pair-permuted so S-phase B-fragments are single LDS.64 (stride 72,
// conflict-free). K copied via coalesced 4B cp.async (permute-compatible);
// V stays on the 16B cp.async path.
// =====================================================================
__global__ __launch_bounds__(256, 2) void flash_mma_kernel()
{
    extern __shared__ uint32_t smu[];
    uint32_t* KsB = smu;                  // 2 x [64][KRS] rows+cols permuted
    uint32_t* VsB = smu + 2 * KB_WORDS;   // 2 x [64][VRS] natural

    const int t    = threadIdx.x;
    const int warp = t >> 5;
    const int lane = t & 31;
    const int gid  = lane >> 2;
    const int tig  = lane & 3;
    const int q0   = blockIdx.x * 128;
    const int bh   = blockIdx.y;

    const float* qb = g_q + (size_t)bh * SEQ * DK;
    const float* kb = g_k + (size_t)bh * SEQ * DK;
    const float* vb = g_v + (size_t)bh * SEQ * DK;

    const int r0 = q0 + warp * 16 + gid;
    const int r1 = r0 + 8;
    uint32_t qf[8][4];
#pragma unroll
    for (int kk = 0; kk < 8; kk++) {
        qf[kk][0] = f2tf(qb[(size_t)r0 * DK + kk * 8 + tig]     * 0.125f);
        qf[kk][1] = f2tf(qb[(size_t)r1 * DK + kk * 8 + tig]     * 0.125f);
        qf[kk][2] = f2tf(qb[(size_t)r0 * DK + kk * 8 + tig + 4] * 0.125f);
        qf[kk][3] = f2tf(qb[(size_t)r1 * DK + kk * 8 + tig + 4] * 0.125f);
    }

    float m0 = -INFINITY, m1 = -INFINITY, l0 = 0.f, l1 = 0.f;
    float o[8][4];
#pragma unroll
    for (int j = 0; j < 8; j++)
#pragma unroll
        for (int k = 0; k < 4; k++) o[j][k] = 0.f;

    // V copy coords (16B chunks): 4 per thread
    const int crow[4] = { (t + 0) >> 4, (t + 256) >> 4, (t + 512) >> 4, (t + 768) >> 4 };
    const int cc4     = (t & 15) << 2;

    // K copy coords (4B words, coalesced): col fixed per thread, rows step by 4
    const int kcol   = t & 63;
    const int kcperm = (kcol & ~7) | ((kcol & 3) << 1) | ((kcol >> 2) & 1);
    const int kr0    = t >> 6;   // 0..3

    auto issue_kv = [&](int buf, int s0) {
        uint32_t* Ks_ = KsB + buf * KB_WORDS;
        uint32_t* Vs_ = VsB + buf * VB_WORDS;
#pragma unroll
        for (int i = 0; i < 16; i++) {
            int row  = kr0 + 4 * i;
            int prow = (row & ~7) | ((row & 3) << 1) | ((row >> 2) & 1);
            cpa4(Ks_ + prow * KRS + kcperm, kb + (size_t)(s0 + row) * DK + kcol);
        }
#pragma unroll
        for (int rep = 0; rep < 4; rep++) {
            int row = crow[rep];
            cpa16(Vs_ + row * VRS + cc4, vb + (size_t)(s0 + row) * DK + cc4);
        }
        cpa_commit();
    };

    issue_kv(0, 0);

    for (int tile = 0; tile < SEQ / 64; tile++) {
        const int buf = tile & 1;
        uint32_t* Ks = KsB + buf * KB_WORDS;
        uint32_t* Vs = VsB + buf * VB_WORDS;

        cpa_wait<0>();
        __syncthreads();
        if (tile + 1 < SEQ / 64) issue_kv(buf ^ 1, (tile + 1) * 64);

        // ---- S = Q K^T (B-fragment = one LDS.64) ----
        float sacc[8][4];
#pragma unroll
        for (int j = 0; j < 8; j++)
#pragma unroll
            for (int k = 0; k < 4; k++) sacc[j][k] = 0.f;
#pragma unroll
        for (int kk = 0; kk < 8; kk++) {
#pragma unroll
            for (int j = 0; j < 8; j++) {
                uint2 b = *(const uint2*)&Ks[(j * 8 + gid) * KRS + kk * 8 + 2 * tig];
                mma_tf32_v(sacc[j], qf[kk], b.x, b.y);
            }
        }

        // ---- fragment-resident online softmax ----
        float t0 = -INFINITY, t1 = -INFINITY;
#pragma unroll
        for (int j = 0; j < 8; j++) {
            t0 = fmaxf(t0, fmaxf(sacc[j][0], sacc[j][1]));
            t1 = fmaxf(t1, fmaxf(sacc[j][2], sacc[j][3]));
        }
        t0 = fmaxf(t0, __shfl_xor_sync(0xffffffffu, t0, 1));
        t0 = fmaxf(t0, __shfl_xor_sync(0xffffffffu, t0, 2));
        t1 = fmaxf(t1, __shfl_xor_sync(0xffffffffu, t1, 1));
        t1 = fmaxf(t1, __shfl_xor_sync(0xffffffffu, t1, 2));

        float nm0 = fmaxf(m0, t0), nm1 = fmaxf(m1, t1);
        float a0 = __expf(m0 - nm0), a1 = __expf(m1 - nm1);
        m0 = nm0; m1 = nm1;

        float p0 = 0.f, p1 = 0.f;
#pragma unroll
        for (int j = 0; j < 8; j++) {
            float e0 = __expf(sacc[j][0] - nm0);
            float e1 = __expf(sacc[j][1] - nm0);
            float e2 = __expf(sacc[j][2] - nm1);
            float e3 = __expf(sacc[j][3] - nm1);
            p0 += e0 + e1;
            p1 += e2 + e3;
            sacc[j][0] = __uint_as_float(f2tf(e0));
            sacc[j][1] = __uint_as_float(f2tf(e1));
            sacc[j][2] = __uint_as_float(f2tf(e2));
            sacc[j][3] = __uint_as_float(f2tf(e3));
        }
        p0 += __shfl_xor_sync(0xffffffffu, p0, 1);
        p0 += __shfl_xor_sync(0xffffffffu, p0, 2);
        p1 += __shfl_xor_sync(0xffffffffu, p1, 1);
        p1 += __shfl_xor_sync(0xffffffffu, p1, 2);
        l0 = l0 * a0 + p0;
        l1 = l1 * a1 + p1;

#pragma unroll
        for (int j = 0; j < 8; j++) {
            o[j][0] *= a0; o[j][1] *= a0;
            o[j][2] *= a1; o[j][3] *= a1;
        }

        // ---- O += P V (P in registers, A-frag order {e0,e2,e1,e3}) ----
#pragma unroll
        for (int kk = 0; kk < 8; kk++) {
            uint32_t af[4];
            af[0] = __float_as_uint(sacc[kk][0]);
            af[1] = __float_as_uint(sacc[kk][2]);
            af[2] = __float_as_uint(sacc[kk][1]);
            af[3] = __float_as_uint(sacc[kk][3]);
#pragma unroll
            for (int j = 0; j < 8; j++) {
                uint32_t bf[2];
                bf[0] = Vs[(kk * 8 + tig) * VRS + j * 8 + gid];
                bf[1] = Vs[(kk * 8 + tig + 4) * VRS + j * 8 + gid];
                mma_tf32(o[j], af, bf);
            }
        }
    }

    const float i0 = 1.f / l0, i1 = 1.f / l1;
    const int b_ = bh >> 4, h = bh & 15;
    float* row0 = g_cat + (size_t)(b_ * SEQ + r0) * D_MODEL + h * DK;
    float* row1 = g_cat + (size_t)(b_ * SEQ + r1) * D_MODEL + h * DK;
#pragma unroll
    for (int j = 0; j < 8; j++) {
        *(float2*)(row0 + j * 8 + tig * 2) = make_float2(o[j][0] * i0, o[j][1] * i0);
        *(float2*)(row1 + j * 8 + tig * 2) = make_float2(o[j][2] * i1, o[j][3] * i1);
    }
}

extern "C" void kernel_launch(void* const* d_in, const int* in_sizes, int n_in,
                              void* d_out, int out_size)
{
    const float* Q  = (const float*)d_in[0];
    const float* K  = (const float*)d_in[1];
    const float* V  = (const float*)d_in[2];
    const float* Wq = (const float*)d_in[3];
    const float* bq = (const float*)d_in[4];
    const float* Wk = (const float*)d_in[5];
    const float* bk = (const float*)d_in[6];
    const float* Wv = (const float*)d_in[7];
    const float* bv = (const float*)d_in[8];
    const float* Wo = (const float*)d_in[9];
    const float* bo = (const float*)d_in[10];
    float* out = (float*)d_out;

    float *gq, *gk, *gv, *gcat;
    cudaGetSymbolAddress((void**)&gq, g_q);
    cudaGetSymbolAddress((void**)&gk, g_k);
    cudaGetSymbolAddress((void**)&gv, g_v);
    cudaGetSymbolAddress((void**)&gcat, g_cat);

    const int proj_smem  = (NSTAGE * A_STAGE_WORDS + NSTAGE * B0_STAGE_WORDS) * 4; // 75776
    const int outg_smem  = (NSTAGE * A_STAGE_WORDS + NSTAGE * B1_STAGE_WORDS) * 4; // 81920
    const int flash_smem = (2 * KB_WORDS + 2 * VB_WORDS) * 4;                      // 73728

    cudaFuncSetAttribute(proj_gemm3_v3_kernel,
                         cudaFuncAttributeMaxDynamicSharedMemorySize, proj_smem);
    cudaFuncSetAttribute(gemm_v3_kernel<1>,
                         cudaFuncAttributeMaxDynamicSharedMemorySize, outg_smem);
    cudaFuncSetAttribute(flash_mma_kernel,
                         cudaFuncAttributeMaxDynamicSharedMemorySize, flash_smem);

    ProjArgs pa;
    pa.X[0] = Q;  pa.X[1] = K;  pa.X[2] = V;
    pa.W[0] = Wq; pa.W[1] = Wk; pa.W[2] = Wv;
    pa.bias[0] = bq; pa.bias[1] = bk; pa.bias[2] = bv;
    pa.out[0] = gq; pa.out[1] = gk; pa.out[2] = gv;

    dim3 pgrd(D_MODEL / 128, M_TOTAL / 128, 3);
    proj_gemm3_v3_kernel<<<pgrd, dim3(256), proj_smem>>>(pa);

    dim3 fgrd(SEQ / 128, BATCH * NUM_HEADS);
    flash_mma_kernel<<<fgrd, dim3(256), flash_smem>>>();

    dim3 ogrd(D_MODEL / 128, M_TOTAL / 128);
    gemm_v3_kernel<1><<<ogrd, dim3(256), outg_smem>>>(gcat, Wo, bo, out);
}

// round 12
// speedup vs baseline: 1.0608x; 1.0608x over previous
#include <cuda_runtime.h>
#include <math.h>
#include <stdint.h>

#define D_MODEL 1024
#define NUM_HEADS 16
#define DK 64
#define BATCH 2
#define SEQ 2048
#define M_TOTAL (BATCH * SEQ)  // 4096

// GEMM smem geometry
#define A_ROW_STRIDE 20
#define A_STAGE_WORDS (128 * A_ROW_STRIDE)
#define B0_STAGE_WORDS (16 * 136)
#define B1_STAGE_WORDS (128 * A_ROW_STRIDE)
#define NSTAGE 4      // out-GEMM
#define PSTAGE 6      // proj GEMM (double-chunk barriers)

// flash smem strides (R9, known-good): K/P loads gid*stride+tig -> stride%32==4;
// V loads tig*stride+gid -> stride%32==8.
#define KRS 68
#define VRS 72
#define KB_WORDS (64 * KRS)     // 4352 per buffer
#define VB_WORDS (64 * VRS)     // 4608 per buffer

__device__ float g_q[BATCH * NUM_HEADS * SEQ * DK];
__device__ float g_k[BATCH * NUM_HEADS * SEQ * DK];
__device__ float g_v[BATCH * NUM_HEADS * SEQ * DK];
__device__ float g_cat[M_TOTAL * D_MODEL];

__device__ __forceinline__ uint32_t f2tf(float f) {
    uint32_t u;
    asm("cvt.rna.tf32.f32 %0, %1;" : "=r"(u) : "f"(f));
    return u;
}

__device__ __forceinline__ void mma_tf32(float* c, const uint32_t* a, const uint32_t* b) {
    asm volatile(
        "mma.sync.aligned.m16n8k8.row.col.f32.tf32.tf32.f32 "
        "{%0,%1,%2,%3}, {%4,%5,%6,%7}, {%8,%9}, {%0,%1,%2,%3};"
        : "+f"(c[0]), "+f"(c[1]), "+f"(c[2]), "+f"(c[3])
        : "r"(a[0]), "r"(a[1]), "r"(a[2]), "r"(a[3]), "r"(b[0]), "r"(b[1]));
}

__device__ __forceinline__ void cpa16(uint32_t* smem_dst, const float* gsrc) {
    uint32_t s = (uint32_t)__cvta_generic_to_shared(smem_dst);
    asm volatile("cp.async.cg.shared.global [%0], [%1], 16;" :: "r"(s), "l"(gsrc));
}
__device__ __forceinline__ void cpa_commit() {
    asm volatile("cp.async.commit_group;");
}
template <int N>
__device__ __forceinline__ void cpa_wait() {
    asm volatile("cp.async.wait_group %0;" :: "n"(N));
}

// =====================================================================
// Out-projection GEMM (R7-R9 template, known-good): NSTAGE=4, one
// sync per k-chunk. MODE 1: out[m,n] = X @ Wo[n,:]^T + bo
// =====================================================================
template <int MODE>
__global__ __launch_bounds__(256, 2) void gemm_v3_kernel(
    const float* __restrict__ X, const float* __restrict__ W,
    const float* __restrict__ bias, float* __restrict__ out)
{
    extern __shared__ uint32_t sg[];
    uint32_t* smA = sg;
    uint32_t* smB = sg + NSTAGE * A_STAGE_WORDS;
    const int BSTW = (MODE == 0) ? B0_STAGE_WORDS : B1_STAGE_WORDS;

    const int t    = threadIdx.x;
    const int n0   = blockIdx.x * 128;
    const int m0   = blockIdx.y * 128;
    const int warp = t >> 5;
    const int lane = t & 31;
    const int gid  = lane >> 2;
    const int tig  = lane & 3;
    const int wm   = (warp & 1) * 64;
    const int wn   = (warp >> 1) * 32;

    const int am[2] = { (t + 0) >> 2, (t + 256) >> 2 };
    const int ak4   = (t & 3) << 2;

    float acc[4][4][4];
#pragma unroll
    for (int i = 0; i < 4; i++)
#pragma unroll
        for (int j = 0; j < 4; j++)
#pragma unroll
            for (int k = 0; k < 4; k++) acc[i][j][k] = 0.f;

    auto issue = [&](int stage, int kc) {
        uint32_t* As_ = smA + stage * A_STAGE_WORDS;
        uint32_t* Bs_ = smB + stage * BSTW;
#pragma unroll
        for (int rep = 0; rep < 2; rep++) {
            int m = am[rep];
            cpa16(As_ + m * A_ROW_STRIDE + ak4,
                  X + (size_t)(m0 + m) * D_MODEL + kc * 16 + ak4);
        }
#pragma unroll
        for (int rep = 0; rep < 2; rep++) {
            int f = t + rep * 256;
            if (MODE == 0) {
                int k = f >> 5, n4 = (f & 31) << 2;
                int bn = n0 + n4;
                int ck = ((k >> 2) & 3) << 2;
                cpa16(Bs_ + k * 136 + (n4 ^ ck),
                      W + (size_t)(bn >> 6) * (D_MODEL * DK)
                        + (size_t)(kc * 16 + k) * DK + (bn & 63));
            } else {
                int n = f >> 2, k4 = (f & 3) << 2;
                cpa16(Bs_ + n * A_ROW_STRIDE + k4,
                      W + (size_t)(n0 + n) * D_MODEL + kc * 16 + k4);
            }
        }
    };

    auto compute = [&](int stage) {
        uint32_t* As_ = smA + stage * A_STAGE_WORDS;
        uint32_t* Bs_ = smB + stage * BSTW;
#pragma unroll
        for (int ks = 0; ks < 2; ks++) {
            const int kb = ks * 8;
            uint32_t af[4][4];
#pragma unroll
            for (int mt = 0; mt < 4; mt++) {
                const int r = (wm + mt * 16 + gid) * A_ROW_STRIDE;
                af[mt][0] = As_[r + kb + tig];
                af[mt][1] = As_[r + 8 * A_ROW_STRIDE + kb + tig];
                af[mt][2] = As_[r + kb + tig + 4];
                af[mt][3] = As_[r + 8 * A_ROW_STRIDE + kb + tig + 4];
            }
            uint32_t bf[4][2];
#pragma unroll
            for (int nt = 0; nt < 4; nt++) {
                const int ncol = wn + nt * 8 + gid;
                if (MODE == 0) {
                    const int x0 = ks ? 8 : 0;
                    const int x1 = ks ? 12 : 4;
                    bf[nt][0] = Bs_[(kb + tig) * 136 + (ncol ^ x0)];
                    bf[nt][1] = Bs_[(kb + tig + 4) * 136 + (ncol ^ x1)];
                } else {
                    bf[nt][0] = Bs_[ncol * A_ROW_STRIDE + kb + tig];
                    bf[nt][1] = Bs_[ncol * A_ROW_STRIDE + kb + tig + 4];
                }
            }
#pragma unroll
            for (int mt = 0; mt < 4; mt++)
#pragma unroll
                for (int nt = 0; nt < 4; nt++) mma_tf32(acc[mt][nt], af[mt], bf[nt]);
        }
    };

    issue(0, 0); cpa_commit();
    issue(1, 1); cpa_commit();
    issue(2, 2); cpa_commit();
    for (int kc = 0; kc < 64; kc++) {
        cpa_wait<2>();
        __syncthreads();
        compute(kc & 3);
        if (kc + 3 < 64) issue((kc + 3) & 3, kc + 3);
        cpa_commit();
    }

#pragma unroll
    for (int mt = 0; mt < 4; mt++) {
#pragma unroll
        for (int nt = 0; nt < 4; nt++) {
            const int r0 = m0 + wm + mt * 16 + gid;
            const int r1 = r0 + 8;
            const int c  = n0 + wn + nt * 8 + tig * 2;
            const float bv0 = bias[c], bv1 = bias[c + 1];
            float2 v0 = make_float2(acc[mt][nt][0] + bv0, acc[mt][nt][1] + bv1);
            float2 v1 = make_float2(acc[mt][nt][2] + bv0, acc[mt][nt][3] + bv1);
            if (MODE == 0) {
                const int h = c >> 6, kd = c & 63;
                const int b0_ = r0 >> 11, s0 = r0 & 2047;
                const int b1_ = r1 >> 11, s1 = r1 & 2047;
                *(float2*)(out + (((size_t)b0_ * NUM_HEADS + h) * SEQ + s0) * DK + kd) = v0;
                *(float2*)(out + (((size_t)b1_ * NUM_HEADS + h) * SEQ + s1) * DK + kd) = v1;
            } else {
                *(float2*)(out + (size_t)r0 * D_MODEL + c) = v0;
                *(float2*)(out + (size_t)r1 * D_MODEL + c) = v1;
            }
        }
    }
}

// =====================================================================
// Proj GEMM v4b: PSTAGE=6, TWO k-chunks per barrier. Commits are
// UNCONDITIONAL (empty tail groups keep wait<2> draining real groups —
// the R11 race fix).
// =====================================================================
struct ProjArgs {
    const float* X[3];
    const float* W[3];
    const float* bias[3];
    float* out[3];
};

__global__ __launch_bounds__(256, 2) void proj_gemm3_v4_kernel(ProjArgs args)
{
    extern __shared__ uint32_t sg[];
    const int z = blockIdx.z;
    const float* X    = args.X[z];
    const float* W    = args.W[z];
    const float* bias = args.bias[z];
    float* out        = args.out[z];

    uint32_t* smA = sg;
    uint32_t* smB = sg + PSTAGE * A_STAGE_WORDS;

    const int t    = threadIdx.x;
    const int n0   = blockIdx.x * 128;
    const int m0   = blockIdx.y * 128;
    const int warp = t >> 5;
    const int lane = t & 31;
    const int gid  = lane >> 2;
    const int tig  = lane & 3;
    const int wm   = (warp & 1) * 64;
    const int wn   = (warp >> 1) * 32;

    const int am[2] = { (t + 0) >> 2, (t + 256) >> 2 };
    const int ak4   = (t & 3) << 2;

    float acc[4][4][4];
#pragma unroll
    for (int i = 0; i < 4; i++)
#pragma unroll
        for (int j = 0; j < 4; j++)
#pragma unroll
            for (int k = 0; k < 4; k++) acc[i][j][k] = 0.f;

    auto issue = [&](int stage, int kc) {
        uint32_t* As_ = smA + stage * A_STAGE_WORDS;
        uint32_t* Bs_ = smB + stage * B0_STAGE_WORDS;
#pragma unroll
        for (int rep = 0; rep < 2; rep++) {
            int m = am[rep];
            cpa16(As_ + m * A_ROW_STRIDE + ak4,
                  X + (size_t)(m0 + m) * D_MODEL + kc * 16 + ak4);
        }
#pragma unroll
        for (int rep = 0; rep < 2; rep++) {
            int f = t + rep * 256;
            int k = f >> 5, n4 = (f & 31) << 2;
            int bn = n0 + n4;
            int ck = ((k >> 2) & 3) << 2;
            cpa16(Bs_ + k * 136 + (n4 ^ ck),
                  W + (size_t)(bn >> 6) * (D_MODEL * DK)
                    + (size_t)(kc * 16 + k) * DK + (bn & 63));
        }
    };

    auto compute = [&](int stage) {
        uint32_t* As_ = smA + stage * A_STAGE_WORDS;
        uint32_t* Bs_ = smB + stage * B0_STAGE_WORDS;
#pragma unroll
        for (int ks = 0; ks < 2; ks++) {
            const int kb = ks * 8;
            const int x0 = ks ? 8 : 0;
            const int x1 = ks ? 12 : 4;
            uint32_t af[4][4];
#pragma unroll
            for (int mt = 0; mt < 4; mt++) {
                const int r = (wm + mt * 16 + gid) * A_ROW_STRIDE;
                af[mt][0] = As_[r + kb + tig];
                af[mt][1] = As_[r + 8 * A_ROW_STRIDE + kb + tig];
                af[mt][2] = As_[r + kb + tig + 4];
                af[mt][3] = As_[r + 8 * A_ROW_STRIDE + kb + tig + 4];
            }
            uint32_t bf[4][2];
#pragma unroll
            for (int nt = 0; nt < 4; nt++) {
                const int ncol = wn + nt * 8 + gid;
                bf[nt][0] = Bs_[(kb + tig) * 136 + (ncol ^ x0)];
                bf[nt][1] = Bs_[(kb + tig + 4) * 136 + (ncol ^ x1)];
            }
#pragma unroll
            for (int mt = 0; mt < 4; mt++)
#pragma unroll
                for (int nt = 0; nt < 4; nt++) mma_tf32(acc[mt][nt], af[mt], bf[nt]);
        }
    };

    // PSTAGE=6 pipeline, 2 chunks per barrier; UNCONDITIONAL commits.
    issue(0, 0); cpa_commit();
    issue(1, 1); cpa_commit();
    issue(2, 2); cpa_commit();
    issue(3, 3); cpa_commit();
    for (int kc = 0; kc < 64; kc += 2) {
        cpa_wait<2>();          // stages kc, kc+1 guaranteed landed
        __syncthreads();
        compute(kc % PSTAGE);
        compute((kc + 1) % PSTAGE);
        if (kc + 4 < 64) issue((kc + 4) % PSTAGE, kc + 4);
        cpa_commit();           // empty group at tail — keeps drain order
        if (kc + 5 < 64) issue((kc + 5) % PSTAGE, kc + 5);
        cpa_commit();
    }

#pragma unroll
    for (int mt = 0; mt < 4; mt++) {
#pragma unroll
        for (int nt = 0; nt < 4; nt++) {
            const int r0 = m0 + wm + mt * 16 + gid;
            const int r1 = r0 + 8;
            const int c  = n0 + wn + nt * 8 + tig * 2;
            const float bv0 = bias[c], bv1 = bias[c + 1];
            float2 v0 = make_float2(acc[mt][nt][0] + bv0, acc[mt][nt][1] + bv1);
            float2 v1 = make_float2(acc[mt][nt][2] + bv0, acc[mt][nt][3] + bv1);
            const int h = c >> 6, kd = c & 63;
            const int b0_ = r0 >> 11, s0 = r0 & 2047;
            const int b1_ = r1 >> 11, s1 = r1 & 2047;
            *(float2*)(out + (((size_t)b0_ * NUM_HEADS + h) * SEQ + s0) * DK + kd) = v0;
            *(float2*)(out + (((size_t)b1_ * NUM_HEADS + h) * SEQ + s1) * DK + kd) = v1;
        }
    }
}

// =====================================================================
// Flash attention (R9 version, known-good): register-resident P via
// K-row permutation; 16B cp.async double-buffered K/V.
// =====================================================================
__global__ __launch_bounds__(256, 2) void flash_mma_kernel()
{
    extern __shared__ uint32_t smu[];
    uint32_t* KsB = smu;                  // 2 x [64][KRS] (rows permuted)
    uint32_t* VsB = smu + 2 * KB_WORDS;   // 2 x [64][VRS] (rows natural)

    const int t    = threadIdx.x;
    const int warp = t >> 5;
    const int lane = t & 31;
    const int gid  = lane >> 2;
    const int tig  = lane & 3;
    const int q0   = blockIdx.x * 128;
    const int bh   = blockIdx.y;

    const float* qb = g_q + (size_t)bh * SEQ * DK;
    const float* kb = g_k + (size_t)bh * SEQ * DK;
    const float* vb = g_v + (size_t)bh * SEQ * DK;

    const int r0 = q0 + warp * 16 + gid;
    const int r1 = r0 + 8;
    uint32_t qf[8][4];
#pragma unroll
    for (int kk = 0; kk < 8; kk++) {
        qf[kk][0] = f2tf(qb[(size_t)r0 * DK + kk * 8 + tig]     * 0.125f);
        qf[kk][1] = f2tf(qb[(size_t)r1 * DK + kk * 8 + tig]     * 0.125f);
        qf[kk][2] = f2tf(qb[(size_t)r0 * DK + kk * 8 + tig + 4] * 0.125f);
        qf[kk][3] = f2tf(qb[(size_t)r1 * DK + kk * 8 + tig + 4] * 0.125f);
    }

    float m0 = -INFINITY, m1 = -INFINITY, l0 = 0.f, l1 = 0.f;
    float o[8][4];
#pragma unroll
    for (int j = 0; j < 8; j++)
#pragma unroll
        for (int k = 0; k < 4; k++) o[j][k] = 0.f;

    const int crow[4] = { (t + 0) >> 4, (t + 256) >> 4, (t + 512) >> 4, (t + 768) >> 4 };
    const int cc4     = (t & 15) << 2;

    auto issue_kv = [&](int buf, int s0) {
        uint32_t* Ks_ = KsB + buf * KB_WORDS;
        uint32_t* Vs_ = VsB + buf * VB_WORDS;
#pragma unroll
        for (int rep = 0; rep < 4; rep++) {
            int row  = crow[rep];
            int prow = (row & ~7) | ((row & 3) << 1) | ((row >> 2) & 1);
            cpa16(Ks_ + prow * KRS + cc4, kb + (size_t)(s0 + row) * DK + cc4);
            cpa16(Vs_ + row  * VRS + cc4, vb + (size_t)(s0 + row) * DK + cc4);
        }
        cpa_commit();
    };

    issue_kv(0, 0);

    for (int tile = 0; tile < SEQ / 64; tile++) {
        const int buf = tile & 1;
        uint32_t* Ks = KsB + buf * KB_WORDS;
        uint32_t* Vs = VsB + buf * VB_WORDS;

        cpa_wait<0>();
        __syncthreads();
        if (tile + 1 < SEQ / 64) issue_kv(buf ^ 1, (tile + 1) * 64);

        // ---- S = Q K^T (K rows permuted -> C-frag in A-frag order) ----
        float sacc[8][4];
#pragma unroll
        for (int j = 0; j < 8; j++)
#pragma unroll
            for (int k = 0; k < 4; k++) sacc[j][k] = 0.f;
#pragma unroll
        for (int kk = 0; kk < 8; kk++) {
            uint32_t bf[8][2];
#pragma unroll
            for (int j = 0; j < 8; j++) {
                bf[j][0] = Ks[(j * 8 + gid) * KRS + kk * 8 + tig];
                bf[j][1] = Ks[(j * 8 + gid) * KRS + kk * 8 + tig + 4];
            }
#pragma unroll
            for (int j = 0; j < 8; j++) mma_tf32(sacc[j], qf[kk], bf[j]);
        }

        // ---- fragment-resident online softmax ----
        float t0 = -INFINITY, t1 = -INFINITY;
#pragma unroll
        for (int j = 0; j < 8; j++) {
            t0 = fmaxf(t0, fmaxf(sacc[j][0], sacc[j][1]));
            t1 = fmaxf(t1, fmaxf(sacc[j][2], sacc[j][3]));
        }
        t0 = fmaxf(t0, __shfl_xor_sync(0xffffffffu, t0, 1));
        t0 = fmaxf(t0, __shfl_xor_sync(0xffffffffu, t0, 2));
        t1 = fmaxf(t1, __shfl_xor_sync(0xffffffffu, t1, 1));
        t1 = fmaxf(t1, __shfl_xor_sync(0xffffffffu, t1, 2));

        float nm0 = fmaxf(m0, t0), nm1 = fmaxf(m1, t1);
        float a0 = __expf(m0 - nm0), a1 = __expf(m1 - nm1);
        m0 = nm0; m1 = nm1;

        float p0 = 0.f, p1 = 0.f;
#pragma unroll
        for (int j = 0; j < 8; j++) {
            float e0 = __expf(sacc[j][0] - nm0);
            float e1 = __expf(sacc[j][1] - nm0);
            float e2 = __expf(sacc[j][2] - nm1);
            float e3 = __expf(sacc[j][3] - nm1);
            p0 += e0 + e1;
            p1 += e2 + e3;
            sacc[j][0] = __uint_as_float(f2tf(e0));
            sacc[j][1] = __uint_as_float(f2tf(e1));
            sacc[j][2] = __uint_as_float(f2tf(e2));
            sacc[j][3] = __uint_as_float(f2tf(e3));
        }
        p0 += __shfl_xor_sync(0xffffffffu, p0, 1);
        p0 += __shfl_xor_sync(0xffffffffu, p0, 2);
        p1 += __shfl_xor_sync(0xffffffffu, p1, 1);
        p1 += __shfl_xor_sync(0xffffffffu, p1, 2);
        l0 = l0 * a0 + p0;
        l1 = l1 * a1 + p1;

#pragma unroll
        for (int j = 0; j < 8; j++) {
            o[j][0] *= a0; o[j][1] *= a0;
            o[j][2] *= a1; o[j][3] *= a1;
        }

        // ---- O += P V (P in registers, A-frag order {e0,e2,e1,e3}) ----
#pragma unroll
        for (int kk = 0; kk < 8; kk++) {
            uint32_t af[4];
            af[0] = __float_as_uint(sacc[kk][0]);
            af[1] = __float_as_uint(sacc[kk][2]);
            af[2] = __float_as_uint(sacc[kk][1]);
            af[3] = __float_as_uint(sacc[kk][3]);
#pragma unroll
            for (int j = 0; j < 8; j++) {
                uint32_t bf[2];
                bf[0] = Vs[(kk * 8 + tig) * VRS + j * 8 + gid];
                bf[1] = Vs[(kk * 8 + tig + 4) * VRS + j * 8 + gid];
                mma_tf32(o[j], af, bf);
            }
        }
    }

    const float i0 = 1.f / l0, i1 = 1.f / l1;
    const int b_ = bh >> 4, h = bh & 15;
    float* row0 = g_cat + (size_t)(b_ * SEQ + r0) * D_MODEL + h * DK;
    float* row1 = g_cat + (size_t)(b_ * SEQ + r1) * D_MODEL + h * DK;
#pragma unroll
    for (int j = 0; j < 8; j++) {
        *(float2*)(row0 + j * 8 + tig * 2) = make_float2(o[j][0] * i0, o[j][1] * i0);
        *(float2*)(row1 + j * 8 + tig * 2) = make_float2(o[j][2] * i1, o[j][3] * i1);
    }
}

extern "C" void kernel_launch(void* const* d_in, const int* in_sizes, int n_in,
                              void* d_out, int out_size)
{
    const float* Q  = (const float*)d_in[0];
    const float* K  = (const float*)d_in[1];
    const float* V  = (const float*)d_in[2];
    const float* Wq = (const float*)d_in[3];
    const float* bq = (const float*)d_in[4];
    const float* Wk = (const float*)d_in[5];
    const float* bk = (const float*)d_in[6];
    const float* Wv = (const float*)d_in[7];
    const float* bv = (const float*)d_in[8];
    const float* Wo = (const float*)d_in[9];
    const float* bo = (const float*)d_in[10];
    float* out = (float*)d_out;

    float *gq, *gk, *gv, *gcat;
    cudaGetSymbolAddress((void**)&gq, g_q);
    cudaGetSymbolAddress((void**)&gk, g_k);
    cudaGetSymbolAddress((void**)&gv, g_v);
    cudaGetSymbolAddress((void**)&gcat, g_cat);

    const int proj_smem  = (PSTAGE * (A_STAGE_WORDS + B0_STAGE_WORDS)) * 4;        // 113664
    const int outg_smem  = (NSTAGE * A_STAGE_WORDS + NSTAGE * B1_STAGE_WORDS) * 4; // 81920
    const int flash_smem = (2 * KB_WORDS + 2 * VB_WORDS) * 4;                      // 71680

    cudaFuncSetAttribute(proj_gemm3_v4_kernel,
                         cudaFuncAttributeMaxDynamicSharedMemorySize, proj_smem);
    cudaFuncSetAttribute(gemm_v3_kernel<1>,
                         cudaFuncAttributeMaxDynamicSharedMemorySize, outg_smem);
    cudaFuncSetAttribute(flash_mma_kernel,
                         cudaFuncAttributeMaxDynamicSharedMemorySize, flash_smem);

    ProjArgs pa;
    pa.X[0] = Q;  pa.X[1] = K;  pa.X[2] = V;
    pa.W[0] = Wq; pa.W[1] = Wk; pa.W[2] = Wv;
    pa.bias[0] = bq; pa.bias[1] = bk; pa.bias[2] = bv;
    pa.out[0] = gq; pa.out[1] = gk; pa.out[2] = gv;

    dim3 pgrd(D_MODEL / 128, M_TOTAL / 128, 3);
    proj_gemm3_v4_kernel<<<pgrd, dim3(256), proj_smem>>>(pa);

    dim3 fgrd(SEQ / 128, BATCH * NUM_HEADS);
    flash_mma_kernel<<<fgrd, dim3(256), flash_smem>>>();

    dim3 ogrd(D_MODEL / 128, M_TOTAL / 128);
    gemm_v3_kernel<1><<<ogrd, dim3(256), outg_smem>>>(gcat, Wo, bo, out);
}